// round 12
// baseline (speedup 1.0000x reference)
#include <cuda_runtime.h>
#include <cstdint>
#include <cfloat>

#define B_     256
#define C_     2048
#define K_     18        // landmarks (GEMM N)
#define HW_    192       // GEMM K
#define TPB    256
#define ROWS   128       // c-rows per item (GEMM M tile); 16 rows per warp
#define NPAD   24        // N padded to 3x8
#define NT     3
#define STAGE_K 16
#define NSTG   (HW_/STAGE_K)   // 12
#define NBUF   3
#define BSTRIDE 196      // 196 mod 32 = 4 -> B frag LDS conflict-free

#define NTILE  (C_/ROWS)            // 16 m-tiles per b
#define NITEMS (B_*NTILE)           // 4096 work items
#define GRID   608                  // 4 CTAs x 152 SMs, one resident wave

#define SM_B_WORDS (NPAD*BSTRIDE)            // 4704
#define SM_A_WORDS (ROWS*STAGE_K)            // 2048 per buffer
#define SM_CTRL_WORDS 4
#define SMEM_TOTAL ((SM_B_WORDS + NBUF*SM_A_WORDS + SM_CTRL_WORDS)*4)   // 43,408 B

__device__ unsigned int g_item;

// quad swizzle: quad q of row r lives at q ^ ((r>>1)&3)
__device__ __forceinline__ int aswz(int row, int q) { return q ^ ((row >> 1) & 3); }

__device__ __forceinline__ uint32_t s2u(const void* p) {
    uint32_t a;
    asm("{ .reg .u64 t; cvta.to.shared.u64 t, %1; cvt.u32.u64 %0, t; }" : "=r"(a) : "l"(p));
    return a;
}
// cp.async with whole-line L2 prefetch: DRAM sees clean 128B-line streams.
__device__ __forceinline__ void cpasync16(uint32_t s, const void* g) {
    asm volatile("cp.async.cg.shared.global.L2::128B [%0], [%1], 16;" :: "r"(s), "l"(g));
}
__device__ __forceinline__ void cp_commit() { asm volatile("cp.async.commit_group;" ::: "memory"); }
template <int N> __device__ __forceinline__ void cp_wait() {
    asm volatile("cp.async.wait_group %0;" :: "n"(N) : "memory");
}
__device__ __forceinline__ uint32_t f2tf32(float f) {
    uint32_t r;
    asm("cvt.rna.tf32.f32 %0, %1;" : "=r"(r) : "f"(f));
    return r;
}
__device__ __forceinline__ void mma_tf32(float& d0, float& d1, float& d2, float& d3,
                                         uint32_t a0, uint32_t a1, uint32_t a2, uint32_t a3,
                                         uint32_t b0, uint32_t b1) {
    asm volatile("mma.sync.aligned.m16n8k8.row.col.f32.tf32.tf32.f32 "
                 "{%0,%1,%2,%3}, {%4,%5,%6,%7}, {%8,%9}, {%0,%1,%2,%3};"
                 : "+f"(d0), "+f"(d1), "+f"(d2), "+f"(d3)
                 : "r"(a0), "r"(a1), "r"(a2), "r"(a3), "r"(b0), "r"(b1));
}
__device__ __forceinline__ float shfl_xor_max(float v, int m) {
    float r;
    asm volatile("shfl.sync.bfly.b32 %0, %1, %2, 0x1F, 0xFFFFFFFF;" : "=f"(r) : "f"(v), "r"(m));
    return fmaxf(v, r);
}

extern __shared__ float smem[];

__global__ void pgfa_init_kernel() { g_item = GRID; }

__global__ __launch_bounds__(TPB, 4)
void pgfa_mma_kernel(const float* __restrict__ feat,
                     const float* __restrict__ masks,
                     const float* __restrict__ pgf,
                     float* __restrict__ out)
{
    uint32_t* s_b = reinterpret_cast<uint32_t*>(smem);          // [NPAD][BSTRIDE] tf32 bits
    float*    s_a = smem + SM_B_WORDS;                          // NBUF x [ROWS][16] swizzled
    int*      sn  = reinterpret_cast<int*>(smem + SM_B_WORDS + NBUF * SM_A_WORDS); // [2]

    const int tid  = threadIdx.x;
    const int wid  = tid >> 5;
    const int lane = tid & 31;
    const int gid  = lane >> 2;
    const int tig  = lane & 3;
    const int wbase = wid * 16;          // this warp's private 16-row slice
    const uint32_t sabase = s2u(s_a);

    // Per-WARP stage load: 16 rows x 16 floats = 64 float4, 2 per lane.
    auto issue_stage = [&](const float* fb, int s, int buf) {
        uint32_t sbm = sabase + (uint32_t)(buf * SM_A_WORDS) * 4;
        const int k0 = s * STAGE_K;
        #pragma unroll
        for (int q = 0; q < 2; q++) {
            int flat = q * 32 + lane;
            int row  = wbase + (flat >> 2);
            int c4   = flat & 3;
            cpasync16(sbm + (uint32_t)(row * STAGE_K + aswz(row, c4) * 4) * 4,
                      fb + (size_t)row * HW_ + k0 + c4 * 4);
        }
        cp_commit();
    };

    auto stage_B = [&](int b) {
        const float* msrc = masks + (size_t)b * K_ * HW_;
        for (int i = tid; i < K_ * HW_; i += TPB) {
            int n = i / HW_, k = i - n * HW_;
            s_b[n * BSTRIDE + k] = f2tf32(msrc[i]);
        }
        for (int i = tid; i < (NPAD - K_) * HW_; i += TPB) {
            int n = K_ + i / HW_, k = i % HW_;
            s_b[n * BSTRIDE + k] = 0u;
        }
    };

    int item = blockIdx.x;
    if (item >= NITEMS) return;
    int cur_b = item >> 4;

    stage_B(cur_b);
    if (tid == 0) sn[0] = (int)atomicAdd(&g_item, 1u);
    __syncthreads();                     // publish s_b + sn[0]
    int nxt = sn[0];
    int bp  = 1;                         // ping-pong slot for the next boundary

    const float* fbase = feat + ((size_t)cur_b * C_ + (item & (NTILE - 1)) * ROWS) * HW_;

    while (true) {
        // early steal: ATOMG latency hidden behind this whole item
        if (tid == 0) sn[bp] = (int)atomicAdd(&g_item, 1u);

        const int rowbase = (item & (NTILE - 1)) * ROWS;
        const size_t orow = (size_t)(item >> 4) * (2 * C_);

        // pgf copy half (overlaps the feat stream)
        if (tid < ROWS)
            out[orow + rowbase + tid] = pgf[(size_t)(item >> 4) * C_ + rowbase + tid];

        issue_stage(fbase, 0, 0);
        issue_stage(fbase, 1, 1);

        float d[NT][4];
        #pragma unroll
        for (int nt = 0; nt < NT; nt++)
            #pragma unroll
            for (int j = 0; j < 4; j++) d[nt][j] = 0.0f;

        #pragma unroll 1
        for (int s = 0; s < NSTG; s++) {
            if (s < NSTG - 1) cp_wait<1>();          // this warp's stage s landed
            else              cp_wait<0>();
            if (s + 2 < NSTG) issue_stage(fbase, s + 2, (s + 2) % NBUF);

            const float* abuf = s_a + (s % NBUF) * SM_A_WORDS;

            #pragma unroll
            for (int kc = 0; kc < 2; kc++) {
                const int kl = kc * 8;
                const int kg = s * STAGE_K + kl;
                uint32_t bf[NT][2];
                #pragma unroll
                for (int nt = 0; nt < NT; nt++) {
                    int n = nt * 8 + gid;
                    bf[nt][0] = s_b[n * BSTRIDE + kg + tig];       // tf32 bits, no cvt
                    bf[nt][1] = s_b[n * BSTRIDE + kg + tig + 4];
                }
                const int r0 = wbase + gid;
                const int r1 = r0 + 8;
                const int kq0 = kl >> 2;
                // raw fp32 bits -> tf32 datapath truncates low mantissa (no cvt)
                uint32_t a0 = __float_as_uint(abuf[r0 * STAGE_K + aswz(r0, kq0)     * 4 + tig]);
                uint32_t a1 = __float_as_uint(abuf[r1 * STAGE_K + aswz(r1, kq0)     * 4 + tig]);
                uint32_t a2 = __float_as_uint(abuf[r0 * STAGE_K + aswz(r0, kq0 + 1) * 4 + tig]);
                uint32_t a3 = __float_as_uint(abuf[r1 * STAGE_K + aswz(r1, kq0 + 1) * 4 + tig]);
                #pragma unroll
                for (int nt = 0; nt < NT; nt++)
                    mma_tf32(d[nt][0], d[nt][1], d[nt][2], d[nt][3],
                             a0, a1, a2, a3, bf[nt][0], bf[nt][1]);
            }
        }

        // ---- epilogue: max over n (exclude pad), scale 1/HW, store ----
        {
            const float inv = 1.0f / (float)HW_;
            float m0 = -FLT_MAX, m1 = -FLT_MAX;
            #pragma unroll
            for (int nt = 0; nt < NT; nt++)
                #pragma unroll
                for (int j = 0; j < 2; j++) {
                    int n = nt * 8 + tig * 2 + j;
                    if (n < K_) {
                        m0 = fmaxf(m0, d[nt][j]);
                        m1 = fmaxf(m1, d[nt][2 + j]);
                    }
                }
            m0 = shfl_xor_max(m0, 1); m0 = shfl_xor_max(m0, 2);
            m1 = shfl_xor_max(m1, 1); m1 = shfl_xor_max(m1, 2);
            if (tig == 0) {
                int r = rowbase + wbase + gid;
                out[orow + C_ + r]     = m0 * inv;
                out[orow + C_ + r + 8] = m1 * inv;
            }
        }

        if (nxt >= NITEMS) break;

        const int nb = nxt >> 4;
        __syncthreads();                  // all warps done with s_b; sn[bp] visible
        if (nb != cur_b) {                // rare: b changes every 16 items
            stage_B(nb);
            cur_b = nb;
            __syncthreads();
        }
        item  = nxt;
        fbase = feat + ((size_t)nb * C_ + (item & (NTILE - 1)) * ROWS) * HW_;
        nxt   = sn[bp];
        bp   ^= 1;
    }
}

extern "C" void kernel_launch(void* const* d_in, const int* in_sizes, int n_in,
                              void* d_out, int out_size)
{
    const float* feat  = (const float*)d_in[0];
    const float* masks = (const float*)d_in[1];
    const float* pgf   = (const float*)d_in[2];
    float*       out   = (float*)d_out;

    cudaFuncSetAttribute(pgfa_mma_kernel,
                         cudaFuncAttributeMaxDynamicSharedMemorySize, SMEM_TOTAL);

    pgfa_init_kernel<<<1, 1>>>();
    pgfa_mma_kernel<<<GRID, TPB, SMEM_TOTAL>>>(feat, masks, pgf, out);
}

// round 13
// speedup vs baseline: 1.0042x; 1.0042x over previous
#include <cuda_runtime.h>
#include <cstdint>
#include <cfloat>

#define B_     256
#define C_     2048
#define K_     18        // landmarks (GEMM N)
#define HW_    192       // GEMM K
#define TPB    256
#define ROWS   256       // c-rows per item (GEMM M tile)
#define NPAD   24        // N padded to 3x8
#define NT     3
#define STAGE_K 16
#define NSTG   (HW_/STAGE_K)   // 12
#define NBUF   3
#define BSTRIDE 196      // 196 mod 32 = 4 -> B frag LDS conflict-free

#define NTILE  (C_/ROWS)            // 8 m-tiles per b
#define NITEMS (B_*NTILE)           // 2048 work items
#define GRID   456                  // 3 CTAs x 152 SMs, one resident wave

#define SM_B_WORDS (NPAD*BSTRIDE)            // 4704
#define SM_A_WORDS (ROWS*STAGE_K)            // 4096 per buffer (swizzled, no pad)
#define SM_CTRL_WORDS 4
#define SMEM_TOTAL ((SM_B_WORDS + NBUF*SM_A_WORDS + SM_CTRL_WORDS)*4)   // ~68 KB

__device__ unsigned int g_item;

// quad swizzle: quad q of row r lives at q ^ ((r>>1)&3)
__device__ __forceinline__ int aswz(int row, int q) { return q ^ ((row >> 1) & 3); }

__device__ __forceinline__ uint32_t s2u(const void* p) {
    uint32_t a;
    asm("{ .reg .u64 t; cvta.to.shared.u64 t, %1; cvt.u32.u64 %0, t; }" : "=r"(a) : "l"(p));
    return a;
}
// cp.async with whole-line L2 prefetch: DRAM sees clean 128B-line streams.
__device__ __forceinline__ void cpasync16(uint32_t s, const void* g) {
    asm volatile("cp.async.cg.shared.global.L2::128B [%0], [%1], 16;" :: "r"(s), "l"(g));
}
__device__ __forceinline__ void cp_commit() { asm volatile("cp.async.commit_group;" ::: "memory"); }
template <int N> __device__ __forceinline__ void cp_wait() {
    asm volatile("cp.async.wait_group %0;" :: "n"(N) : "memory");
}
__device__ __forceinline__ uint32_t f2tf32(float f) {
    uint32_t r;
    asm("cvt.rna.tf32.f32 %0, %1;" : "=r"(r) : "f"(f));
    return r;
}
__device__ __forceinline__ void mma_tf32(float& d0, float& d1, float& d2, float& d3,
                                         uint32_t a0, uint32_t a1, uint32_t a2, uint32_t a3,
                                         uint32_t b0, uint32_t b1) {
    asm volatile("mma.sync.aligned.m16n8k8.row.col.f32.tf32.tf32.f32 "
                 "{%0,%1,%2,%3}, {%4,%5,%6,%7}, {%8,%9}, {%0,%1,%2,%3};"
                 : "+f"(d0), "+f"(d1), "+f"(d2), "+f"(d3)
                 : "r"(a0), "r"(a1), "r"(a2), "r"(a3), "r"(b0), "r"(b1));
}
__device__ __forceinline__ float shfl_xor_max(float v, int m) {
    float r;
    asm volatile("shfl.sync.bfly.b32 %0, %1, %2, 0x1F, 0xFFFFFFFF;" : "=f"(r) : "f"(v), "r"(m));
    return fmaxf(v, r);
}

extern __shared__ float smem[];

__global__ void pgfa_init_kernel() { g_item = GRID; }

__global__ __launch_bounds__(TPB, 3)
void pgfa_mma_kernel(const float* __restrict__ feat,
                     const float* __restrict__ masks,
                     const float* __restrict__ pgf,
                     float* __restrict__ out)
{
    uint32_t* s_b = reinterpret_cast<uint32_t*>(smem);          // [NPAD][BSTRIDE] tf32 bits
    float*    s_a = smem + SM_B_WORDS;                          // NBUF x [ROWS][16] swizzled
    int*      sn  = reinterpret_cast<int*>(smem + SM_B_WORDS + NBUF * SM_A_WORDS); // [2]

    const int tid  = threadIdx.x;
    const int wid  = tid >> 5;
    const int lane = tid & 31;
    const int gid  = lane >> 2;
    const int tig  = lane & 3;
    const int wbase = wid * 32;          // this warp's private 32-row slice
    const uint32_t sabase = s2u(s_a);

    // Per-WARP stage load: 32 rows x 16 floats = 128 float4, 4 per lane.
    auto issue_stage = [&](const float* fb, int s) {
        uint32_t sbm = sabase + (uint32_t)((s % NBUF) * SM_A_WORDS) * 4;
        const int k0 = s * STAGE_K;
        #pragma unroll
        for (int q = 0; q < 4; q++) {
            int flat = q * 32 + lane;
            int row  = wbase + (flat >> 2);
            int c4   = flat & 3;
            cpasync16(sbm + (uint32_t)(row * STAGE_K + aswz(row, c4) * 4) * 4,
                      fb + (size_t)row * HW_ + k0 + c4 * 4);
        }
        cp_commit();
    };

    auto stage_B = [&](int b) {
        const float* msrc = masks + (size_t)b * K_ * HW_;
        for (int i = tid; i < K_ * HW_; i += TPB) {
            int n = i / HW_, k = i - n * HW_;
            s_b[n * BSTRIDE + k] = f2tf32(msrc[i]);
        }
        for (int i = tid; i < (NPAD - K_) * HW_; i += TPB) {
            int n = K_ + i / HW_, k = i % HW_;
            s_b[n * BSTRIDE + k] = 0u;
        }
    };

    int item = blockIdx.x;
    if (item >= NITEMS) return;
    int cur_b = item >> 3;

    stage_B(cur_b);
    if (tid == 0) sn[0] = (int)atomicAdd(&g_item, 1u);
    __syncthreads();                     // publish s_b + sn[0]
    int nxt = sn[0];
    int bp  = 1;

    while (true) {
        // early steal: ATOMG latency hidden behind this whole item
        if (tid == 0) sn[bp] = (int)atomicAdd(&g_item, 1u);

        const int b       = item >> 3;
        const int rowbase = (item & (NTILE - 1)) * ROWS;
        const size_t orow = (size_t)b * (2 * C_);
        const float* fbase = feat + ((size_t)b * C_ + rowbase) * HW_;

        // pgf copy half (overlaps the feat stream)
        out[orow + rowbase + tid] = pgf[(size_t)b * C_ + rowbase + tid];

        float d[2][NT][4];
        #pragma unroll
        for (int mt = 0; mt < 2; mt++)
            #pragma unroll
            for (int nt = 0; nt < NT; nt++)
                #pragma unroll
                for (int j = 0; j < 4; j++) d[mt][nt][j] = 0.0f;

        issue_stage(fbase, 0);
        issue_stage(fbase, 1);

        #pragma unroll 1
        for (int s = 0; s < NSTG; s++) {
            if (s < NSTG - 1) cp_wait<1>();          // this warp's stage s landed
            else              cp_wait<0>();
            if (s + 2 < NSTG) issue_stage(fbase, s + 2);   // warp-private refill, safe

            const float* abuf = s_a + (s % NBUF) * SM_A_WORDS;

            #pragma unroll
            for (int kc = 0; kc < 2; kc++) {
                const int kl = kc * 8;
                const int kg = s * STAGE_K + kl;
                uint32_t bf[NT][2];
                #pragma unroll
                for (int nt = 0; nt < NT; nt++) {
                    int n = nt * 8 + gid;
                    bf[nt][0] = s_b[n * BSTRIDE + kg + tig];       // tf32 bits, no cvt
                    bf[nt][1] = s_b[n * BSTRIDE + kg + tig + 4];
                }
                #pragma unroll
                for (int mt = 0; mt < 2; mt++) {
                    const int r0 = wbase + mt * 16 + gid;
                    const int r1 = r0 + 8;
                    const int kq0 = kl >> 2;
                    // raw fp32 bits -> tf32 datapath truncates low mantissa (no cvt)
                    uint32_t a0 = __float_as_uint(abuf[r0 * STAGE_K + aswz(r0, kq0)     * 4 + tig]);
                    uint32_t a1 = __float_as_uint(abuf[r1 * STAGE_K + aswz(r1, kq0)     * 4 + tig]);
                    uint32_t a2 = __float_as_uint(abuf[r0 * STAGE_K + aswz(r0, kq0 + 1) * 4 + tig]);
                    uint32_t a3 = __float_as_uint(abuf[r1 * STAGE_K + aswz(r1, kq0 + 1) * 4 + tig]);
                    #pragma unroll
                    for (int nt = 0; nt < NT; nt++)
                        mma_tf32(d[mt][nt][0], d[mt][nt][1], d[mt][nt][2], d[mt][nt][3],
                                 a0, a1, a2, a3, bf[nt][0], bf[nt][1]);
                }
            }
        }

        // ---- epilogue: max over n (exclude pad), scale 1/HW, store ----
        const float inv = 1.0f / (float)HW_;
        #pragma unroll
        for (int mt = 0; mt < 2; mt++) {
            float m0 = -FLT_MAX, m1 = -FLT_MAX;
            #pragma unroll
            for (int nt = 0; nt < NT; nt++)
                #pragma unroll
                for (int j = 0; j < 2; j++) {
                    int n = nt * 8 + tig * 2 + j;
                    if (n < K_) {
                        m0 = fmaxf(m0, d[mt][nt][j]);
                        m1 = fmaxf(m1, d[mt][nt][2 + j]);
                    }
                }
            m0 = shfl_xor_max(m0, 1); m0 = shfl_xor_max(m0, 2);
            m1 = shfl_xor_max(m1, 1); m1 = shfl_xor_max(m1, 2);
            if (tig == 0) {
                int r = rowbase + wbase + mt * 16 + gid;
                out[orow + C_ + r]     = m0 * inv;
                out[orow + C_ + r + 8] = m1 * inv;
            }
        }

        if (nxt >= NITEMS) break;

        const int nb = nxt >> 3;
        __syncthreads();                  // sn[bp] visible; all warps done with s_b
        if (nb != cur_b) {                // only 1-in-8 boundaries restage B
            stage_B(nb);
            cur_b = nb;
            __syncthreads();
        }
        item = nxt;
        nxt  = sn[bp];
        bp  ^= 1;
    }
}

extern "C" void kernel_launch(void* const* d_in, const int* in_sizes, int n_in,
                              void* d_out, int out_size)
{
    const float* feat  = (const float*)d_in[0];
    const float* masks = (const float*)d_in[1];
    const float* pgf   = (const float*)d_in[2];
    float*       out   = (float*)d_out;

    cudaFuncSetAttribute(pgfa_mma_kernel,
                         cudaFuncAttributeMaxDynamicSharedMemorySize, SMEM_TOTAL);

    pgfa_init_kernel<<<1, 1>>>();
    pgfa_mma_kernel<<<GRID, TPB, SMEM_TOTAL>>>(feat, masks, pgf, out);
}

// round 14
// speedup vs baseline: 1.1041x; 1.0995x over previous
#include <cuda_runtime.h>
#include <cstdint>
#include <cfloat>

#define B_     256
#define C_     2048
#define K_     18        // landmarks (GEMM N)
#define HW_    192       // GEMM K
#define TPB    256
#define ROWS   256       // c-rows per item (GEMM M tile)
#define NPAD   24        // N padded to 3x8
#define NT     3
#define STAGE_K 16
#define NSTG   (HW_/STAGE_K)   // 12
#define NBUF   3
#define BSTRIDE 196      // 196 mod 32 = 4 -> B frag LDS conflict-free

#define NTILE  (C_/ROWS)            // 8 m-tiles per b
#define NITEMS (B_*NTILE)           // 2048 work items
#define GRID   456                  // 3 CTAs x 152 SMs, one resident wave

#define SM_B_WORDS (NPAD*BSTRIDE)            // 4704
#define SM_A_WORDS (ROWS*STAGE_K)            // 4096 per buffer (swizzled, no pad)
#define SM_CTRL_WORDS 4
#define SMEM_TOTAL ((SM_B_WORDS + NBUF*SM_A_WORDS + SM_CTRL_WORDS)*4)   // ~68 KB

__device__ unsigned int g_item;

// quad swizzle: quad q of row r lives at q ^ ((r>>1)&3)
__device__ __forceinline__ int aswz(int row, int q) { return q ^ ((row >> 1) & 3); }

__device__ __forceinline__ uint32_t s2u(const void* p) {
    uint32_t a;
    asm("{ .reg .u64 t; cvta.to.shared.u64 t, %1; cvt.u32.u64 %0, t; }" : "=r"(a) : "l"(p));
    return a;
}
// cp.async with whole-line L2 prefetch: DRAM sees clean 128B-line streams.
__device__ __forceinline__ void cpasync16(uint32_t s, const void* g) {
    asm volatile("cp.async.cg.shared.global.L2::128B [%0], [%1], 16;" :: "r"(s), "l"(g));
}
__device__ __forceinline__ void cp_commit() { asm volatile("cp.async.commit_group;" ::: "memory"); }
template <int N> __device__ __forceinline__ void cp_wait() {
    asm volatile("cp.async.wait_group %0;" :: "n"(N) : "memory");
}
__device__ __forceinline__ uint32_t f2tf32(float f) {
    uint32_t r;
    asm("cvt.rna.tf32.f32 %0, %1;" : "=r"(r) : "f"(f));
    return r;
}
__device__ __forceinline__ void mma_tf32(float& d0, float& d1, float& d2, float& d3,
                                         uint32_t a0, uint32_t a1, uint32_t a2, uint32_t a3,
                                         uint32_t b0, uint32_t b1) {
    asm volatile("mma.sync.aligned.m16n8k8.row.col.f32.tf32.tf32.f32 "
                 "{%0,%1,%2,%3}, {%4,%5,%6,%7}, {%8,%9}, {%0,%1,%2,%3};"
                 : "+f"(d0), "+f"(d1), "+f"(d2), "+f"(d3)
                 : "r"(a0), "r"(a1), "r"(a2), "r"(a3), "r"(b0), "r"(b1));
}
__device__ __forceinline__ float shfl_xor_max(float v, int m) {
    float r;
    asm volatile("shfl.sync.bfly.b32 %0, %1, %2, 0x1F, 0xFFFFFFFF;" : "=f"(r) : "f"(v), "r"(m));
    return fmaxf(v, r);
}

extern __shared__ float smem[];

__global__ void pgfa_init_kernel() { g_item = GRID; }

__global__ __launch_bounds__(TPB, 3)
void pgfa_mma_kernel(const float* __restrict__ feat,
                     const float* __restrict__ masks,
                     const float* __restrict__ pgf,
                     float* __restrict__ out)
{
    uint32_t* s_b    = reinterpret_cast<uint32_t*>(smem);          // [NPAD][BSTRIDE] tf32 bits
    float*    s_a    = smem + SM_B_WORDS;                          // NBUF x [ROWS][16] swizzled
    int*      s_next = reinterpret_cast<int*>(smem + SM_B_WORDS + NBUF * SM_A_WORDS);

    const int tid  = threadIdx.x;
    const int wid  = tid >> 5;
    const int lane = tid & 31;
    const int gid  = lane >> 2;
    const int tig  = lane & 3;
    const int wbase = wid * 32;          // this warp's private 32-row slice
    const uint32_t sabase = s2u(s_a);

    int item = blockIdx.x;

    while (item < NITEMS) {
        const int b       = item >> 3;           // item / NTILE
        const int rowbase = (item & (NTILE - 1)) * ROWS;

        // ---- pgf copy half (overlaps the feat stream) ----
        const size_t orow = (size_t)b * (2 * C_);
        out[orow + rowbase + tid] = pgf[(size_t)b * C_ + rowbase + tid];

        // ---- stage masks[b] as B [n][k], pre-converted to tf32; pad n>=18 with 0 ----
        {
            const float* msrc = masks + (size_t)b * K_ * HW_;
            for (int i = tid; i < K_ * HW_; i += TPB) {
                int n = i / HW_, k = i - n * HW_;
                s_b[n * BSTRIDE + k] = f2tf32(msrc[i]);
            }
            for (int i = tid; i < (NPAD - K_) * HW_; i += TPB) {
                int n = K_ + i / HW_, k = i % HW_;
                s_b[n * BSTRIDE + k] = 0u;
            }
        }

        const float* fbase = feat + ((size_t)b * C_ + rowbase) * HW_;

        // Per-WARP stage load: 32 rows x 16 floats = 128 float4, 4/lane.
        auto issue_stage = [&](int s) {
            uint32_t sb = sabase + (uint32_t)((s % NBUF) * SM_A_WORDS) * 4;
            const int k0 = s * STAGE_K;
            #pragma unroll
            for (int q = 0; q < 4; q++) {
                int flat = q * 32 + lane;
                int row  = wbase + (flat >> 2);
                int c4   = flat & 3;
                cpasync16(sb + (uint32_t)(row * STAGE_K + aswz(row, c4) * 4) * 4,
                          fbase + (size_t)row * HW_ + k0 + c4 * 4);
            }
            cp_commit();
        };

        float d[2][NT][4];
        #pragma unroll
        for (int mt = 0; mt < 2; mt++)
            #pragma unroll
            for (int nt = 0; nt < NT; nt++)
                #pragma unroll
                for (int j = 0; j < 4; j++) d[mt][nt][j] = 0.0f;

        __syncthreads();      // s_b visible to all warps

        issue_stage(0); issue_stage(1);

        #pragma unroll 1
        for (int s = 0; s < NSTG; s++) {
            if (s < NSTG - 1) cp_wait<1>();          // this warp's stage s landed
            else              cp_wait<0>();
            if (s + 2 < NSTG) issue_stage(s + 2);    // refills (s-1)%3: warp-private, safe

            const float* abuf = s_a + (s % NBUF) * SM_A_WORDS;

            #pragma unroll
            for (int kc = 0; kc < 2; kc++) {
                const int kl = kc * 8;
                const int kg = s * STAGE_K + kl;
                uint32_t bf[NT][2];
                #pragma unroll
                for (int nt = 0; nt < NT; nt++) {
                    int n = nt * 8 + gid;
                    bf[nt][0] = s_b[n * BSTRIDE + kg + tig];       // tf32 bits, no cvt
                    bf[nt][1] = s_b[n * BSTRIDE + kg + tig + 4];
                }
                #pragma unroll
                for (int mt = 0; mt < 2; mt++) {
                    const int r0 = wbase + mt * 16 + gid;
                    const int r1 = r0 + 8;
                    const int kq0 = kl >> 2;
                    // raw fp32 bits -> tf32 datapath truncates low mantissa (no cvt)
                    uint32_t a0 = __float_as_uint(abuf[r0 * STAGE_K + aswz(r0, kq0)     * 4 + tig]);
                    uint32_t a1 = __float_as_uint(abuf[r1 * STAGE_K + aswz(r1, kq0)     * 4 + tig]);
                    uint32_t a2 = __float_as_uint(abuf[r0 * STAGE_K + aswz(r0, kq0 + 1) * 4 + tig]);
                    uint32_t a3 = __float_as_uint(abuf[r1 * STAGE_K + aswz(r1, kq0 + 1) * 4 + tig]);
                    #pragma unroll
                    for (int nt = 0; nt < NT; nt++)
                        mma_tf32(d[mt][nt][0], d[mt][nt][1], d[mt][nt][2], d[mt][nt][3],
                                 a0, a1, a2, a3, bf[nt][0], bf[nt][1]);
                }
            }
        }

        // ---- epilogue: max over n (exclude pad), scale 1/HW, store ----
        const float inv = 1.0f / (float)HW_;
        #pragma unroll
        for (int mt = 0; mt < 2; mt++) {
            float m0 = -FLT_MAX, m1 = -FLT_MAX;
            #pragma unroll
            for (int nt = 0; nt < NT; nt++)
                #pragma unroll
                for (int j = 0; j < 2; j++) {
                    int n = nt * 8 + tig * 2 + j;
                    if (n < K_) {
                        m0 = fmaxf(m0, d[mt][nt][j]);
                        m1 = fmaxf(m1, d[mt][nt][2 + j]);
                    }
                }
            m0 = shfl_xor_max(m0, 1); m0 = shfl_xor_max(m0, 2);
            m1 = shfl_xor_max(m1, 1); m1 = shfl_xor_max(m1, 2);
            if (tig == 0) {
                int r = rowbase + wbase + mt * 16 + gid;
                out[orow + C_ + r]     = m0 * inv;
                out[orow + C_ + r + 8] = m1 * inv;
            }
        }

        // ---- steal next item ----
        if (tid == 0) *s_next = (int)atomicAdd(&g_item, 1u);
        __syncthreads();      // publishes s_next AND all warps done reading s_b
        item = *s_next;
    }
}

extern "C" void kernel_launch(void* const* d_in, const int* in_sizes, int n_in,
                              void* d_out, int out_size)
{
    const float* feat  = (const float*)d_in[0];
    const float* masks = (const float*)d_in[1];
    const float* pgf   = (const float*)d_in[2];
    float*       out   = (float*)d_out;

    cudaFuncSetAttribute(pgfa_mma_kernel,
                         cudaFuncAttributeMaxDynamicSharedMemorySize, SMEM_TOTAL);

    pgfa_init_kernel<<<1, 1>>>();
    pgfa_mma_kernel<<<GRID, TPB, SMEM_TOTAL>>>(feat, masks, pgf, out);
}

// round 15
// speedup vs baseline: 1.1702x; 1.0598x over previous
#include <cuda_runtime.h>
#include <cstdint>
#include <cfloat>

#define B_     256
#define C_     2048
#define K_     18        // landmarks (GEMM N)
#define HW_    192       // GEMM K
#define TPB    256
#define ROWS   256       // c-rows per item (GEMM M tile)
#define NPAD   24        // N padded to 3x8
#define NT     3
#define STAGE_K 16
#define NSTG   (HW_/STAGE_K)   // 12
#define NBUF   3
#define BSTRIDE 196      // 196 mod 32 = 4 -> B frag LDS conflict-free

#define NTILE  (C_/ROWS)            // 8 m-tiles per b
#define NITEMS (B_*NTILE)           // 2048 work items
#define GRID   456                  // 3 CTAs x 152 SMs, one resident wave

#define SM_B_WORDS (NPAD*BSTRIDE)            // 4704
#define SM_A_WORDS (ROWS*STAGE_K)            // 4096 per buffer (swizzled, no pad)
#define SM_CTRL_WORDS 4
#define SMEM_TOTAL ((SM_B_WORDS + NBUF*SM_A_WORDS + SM_CTRL_WORDS)*4)   // ~68 KB

__device__ unsigned int g_item;

// quad swizzle: quad q of row r lives at q ^ ((r>>1)&3)
__device__ __forceinline__ int aswz(int row, int q) { return q ^ ((row >> 1) & 3); }

__device__ __forceinline__ uint32_t s2u(const void* p) {
    uint32_t a;
    asm("{ .reg .u64 t; cvta.to.shared.u64 t, %1; cvt.u32.u64 %0, t; }" : "=r"(a) : "l"(p));
    return a;
}
// cp.async with 256B L2 prefetch: rows are 768B = 3x256B, 256B-aligned, so each
// DRAM row is serviced in 3 activations of 256B instead of 6 of 128B.
__device__ __forceinline__ void cpasync16(uint32_t s, const void* g) {
    asm volatile("cp.async.cg.shared.global.L2::256B [%0], [%1], 16;" :: "r"(s), "l"(g));
}
__device__ __forceinline__ void cp_commit() { asm volatile("cp.async.commit_group;" ::: "memory"); }
template <int N> __device__ __forceinline__ void cp_wait() {
    asm volatile("cp.async.wait_group %0;" :: "n"(N) : "memory");
}
__device__ __forceinline__ uint32_t f2tf32(float f) {
    uint32_t r;
    asm("cvt.rna.tf32.f32 %0, %1;" : "=r"(r) : "f"(f));
    return r;
}
__device__ __forceinline__ void mma_tf32(float& d0, float& d1, float& d2, float& d3,
                                         uint32_t a0, uint32_t a1, uint32_t a2, uint32_t a3,
                                         uint32_t b0, uint32_t b1) {
    asm volatile("mma.sync.aligned.m16n8k8.row.col.f32.tf32.tf32.f32 "
                 "{%0,%1,%2,%3}, {%4,%5,%6,%7}, {%8,%9}, {%0,%1,%2,%3};"
                 : "+f"(d0), "+f"(d1), "+f"(d2), "+f"(d3)
                 : "r"(a0), "r"(a1), "r"(a2), "r"(a3), "r"(b0), "r"(b1));
}
__device__ __forceinline__ float shfl_xor_max(float v, int m) {
    float r;
    asm volatile("shfl.sync.bfly.b32 %0, %1, %2, 0x1F, 0xFFFFFFFF;" : "=f"(r) : "f"(v), "r"(m));
    return fmaxf(v, r);
}

extern __shared__ float smem[];

__global__ void pgfa_init_kernel() { g_item = GRID; }

__global__ __launch_bounds__(TPB, 3)
void pgfa_mma_kernel(const float* __restrict__ feat,
                     const float* __restrict__ masks,
                     const float* __restrict__ pgf,
                     float* __restrict__ out)
{
    uint32_t* s_b    = reinterpret_cast<uint32_t*>(smem);          // [NPAD][BSTRIDE] tf32 bits
    float*    s_a    = smem + SM_B_WORDS;                          // NBUF x [ROWS][16] swizzled
    int*      s_next = reinterpret_cast<int*>(smem + SM_B_WORDS + NBUF * SM_A_WORDS);

    const int tid  = threadIdx.x;
    const int wid  = tid >> 5;
    const int lane = tid & 31;
    const int gid  = lane >> 2;
    const int tig  = lane & 3;
    const int wbase = wid * 32;          // this warp's private 32-row slice
    const uint32_t sabase = s2u(s_a);

    int item = blockIdx.x;

    while (item < NITEMS) {
        const int b       = item >> 3;           // item / NTILE
        const int rowbase = (item & (NTILE - 1)) * ROWS;

        // ---- pgf copy half (overlaps the feat stream) ----
        const size_t orow = (size_t)b * (2 * C_);
        out[orow + rowbase + tid] = pgf[(size_t)b * C_ + rowbase + tid];

        // ---- stage masks[b] as B [n][k], pre-converted to tf32; pad n>=18 with 0 ----
        {
            const float* msrc = masks + (size_t)b * K_ * HW_;
            for (int i = tid; i < K_ * HW_; i += TPB) {
                int n = i / HW_, k = i - n * HW_;
                s_b[n * BSTRIDE + k] = f2tf32(msrc[i]);
            }
            for (int i = tid; i < (NPAD - K_) * HW_; i += TPB) {
                int n = K_ + i / HW_, k = i % HW_;
                s_b[n * BSTRIDE + k] = 0u;
            }
        }

        const float* fbase = feat + ((size_t)b * C_ + rowbase) * HW_;

        // Per-WARP stage load: 32 rows x 16 floats = 128 float4, 4/lane.
        auto issue_stage = [&](int s) {
            uint32_t sb = sabase + (uint32_t)((s % NBUF) * SM_A_WORDS) * 4;
            const int k0 = s * STAGE_K;
            #pragma unroll
            for (int q = 0; q < 4; q++) {
                int flat = q * 32 + lane;
                int row  = wbase + (flat >> 2);
                int c4   = flat & 3;
                cpasync16(sb + (uint32_t)(row * STAGE_K + aswz(row, c4) * 4) * 4,
                          fbase + (size_t)row * HW_ + k0 + c4 * 4);
            }
            cp_commit();
        };

        float d[2][NT][4];
        #pragma unroll
        for (int mt = 0; mt < 2; mt++)
            #pragma unroll
            for (int nt = 0; nt < NT; nt++)
                #pragma unroll
                for (int j = 0; j < 4; j++) d[mt][nt][j] = 0.0f;

        __syncthreads();      // s_b visible to all warps

        issue_stage(0); issue_stage(1);

        #pragma unroll 1
        for (int s = 0; s < NSTG; s++) {
            if (s < NSTG - 1) cp_wait<1>();          // this warp's stage s landed
            else              cp_wait<0>();
            if (s + 2 < NSTG) issue_stage(s + 2);    // refills (s-1)%3: warp-private, safe

            const float* abuf = s_a + (s % NBUF) * SM_A_WORDS;

            #pragma unroll
            for (int kc = 0; kc < 2; kc++) {
                const int kl = kc * 8;
                const int kg = s * STAGE_K + kl;
                uint32_t bf[NT][2];
                #pragma unroll
                for (int nt = 0; nt < NT; nt++) {
                    int n = nt * 8 + gid;
                    bf[nt][0] = s_b[n * BSTRIDE + kg + tig];       // tf32 bits, no cvt
                    bf[nt][1] = s_b[n * BSTRIDE + kg + tig + 4];
                }
                #pragma unroll
                for (int mt = 0; mt < 2; mt++) {
                    const int r0 = wbase + mt * 16 + gid;
                    const int r1 = r0 + 8;
                    const int kq0 = kl >> 2;
                    // raw fp32 bits -> tf32 datapath truncates low mantissa (no cvt)
                    uint32_t a0 = __float_as_uint(abuf[r0 * STAGE_K + aswz(r0, kq0)     * 4 + tig]);
                    uint32_t a1 = __float_as_uint(abuf[r1 * STAGE_K + aswz(r1, kq0)     * 4 + tig]);
                    uint32_t a2 = __float_as_uint(abuf[r0 * STAGE_K + aswz(r0, kq0 + 1) * 4 + tig]);
                    uint32_t a3 = __float_as_uint(abuf[r1 * STAGE_K + aswz(r1, kq0 + 1) * 4 + tig]);
                    #pragma unroll
                    for (int nt = 0; nt < NT; nt++)
                        mma_tf32(d[mt][nt][0], d[mt][nt][1], d[mt][nt][2], d[mt][nt][3],
                                 a0, a1, a2, a3, bf[nt][0], bf[nt][1]);
                }
            }
        }

        // ---- epilogue: max over n (exclude pad), scale 1/HW, store ----
        const float inv = 1.0f / (float)HW_;
        #pragma unroll
        for (int mt = 0; mt < 2; mt++) {
            float m0 = -FLT_MAX, m1 = -FLT_MAX;
            #pragma unroll
            for (int nt = 0; nt < NT; nt++)
                #pragma unroll
                for (int j = 0; j < 2; j++) {
                    int n = nt * 8 + tig * 2 + j;
                    if (n < K_) {
                        m0 = fmaxf(m0, d[mt][nt][j]);
                        m1 = fmaxf(m1, d[mt][nt][2 + j]);
                    }
                }
            m0 = shfl_xor_max(m0, 1); m0 = shfl_xor_max(m0, 2);
            m1 = shfl_xor_max(m1, 1); m1 = shfl_xor_max(m1, 2);
            if (tig == 0) {
                int r = rowbase + wbase + mt * 16 + gid;
                out[orow + C_ + r]     = m0 * inv;
                out[orow + C_ + r + 8] = m1 * inv;
            }
        }

        // ---- steal next item (at END: no claim-ahead, keeps tail balanced) ----
        if (tid == 0) *s_next = (int)atomicAdd(&g_item, 1u);
        __syncthreads();      // publishes s_next AND all warps done reading s_b
        item = *s_next;
    }
}

extern "C" void kernel_launch(void* const* d_in, const int* in_sizes, int n_in,
                              void* d_out, int out_size)
{
    const float* feat  = (const float*)d_in[0];
    const float* masks = (const float*)d_in[1];
    const float* pgf   = (const float*)d_in[2];
    float*       out   = (float*)d_out;

    cudaFuncSetAttribute(pgfa_mma_kernel,
                         cudaFuncAttributeMaxDynamicSharedMemorySize, SMEM_TOTAL);

    pgfa_init_kernel<<<1, 1>>>();
    pgfa_mma_kernel<<<GRID, TPB, SMEM_TOTAL>>>(feat, masks, pgf, out);
}